// round 3
// baseline (speedup 1.0000x reference)
#include <cuda_runtime.h>

// HMM forward (log-space) as a scaled linear recurrence:
//   exp(alpha_t[i]) = exp(L_t) * p_t[i]
//   p_t[i] = (A @ p~_{t-1})[i] / pmax_{t-1} * B[i, obs[t]]   (p~ = unnormalized)
//   alpha_t[i] = L_{t-1} + log(pmax_{t-1} * ... ) folded into L
// Hot loop: pure fp32 matvec + local max reduce; one logf per row per step.
//
// Persistent kernel: 64 CTAs x 512 thr (one wave), one warp per state row,
// A row held in registers (32 floats/lane). Grid barrier = monotonic counter
// (release: fence+RED.ADD, acquire: volatile poll + fence). All cross-CTA
// payload uses .cg (L2-coherent; L1 is NOT coherent across SMs).

#define NZ 1024
#define NX 4096
#define KCTA 64
#define RPC 16         // rows (= warps) per CTA
#define MTHREADS 512

__device__ float        g_Bv[NX * NZ];   // Bv[t*NZ + i] = B[i, obs[t]]  (16 MB)
__device__ float        g_rinvA[NZ];
__device__ float        g_rinvB[NZ];
__device__ float        g_pbuf[2][NZ];
__device__ float        g_L0;
__device__ unsigned int g_count;

// ---------------------------------------------------------------------------
// K1: row sums of transition (1024x1024) and emission (1024x4096) -> 1/sum
// ---------------------------------------------------------------------------
__global__ void k_rowsums(const float* __restrict__ trans,
                          const float* __restrict__ emis) {
    int i = blockIdx.x, tid = threadIdx.x, lane = tid & 31, w = tid >> 5;
    __shared__ float smA[8], smB[8];
    float sA = 0.f, sB = 0.f;
#pragma unroll
    for (int k = 0; k < 4; k++)  sA += trans[i * NZ + tid + 256 * k];
#pragma unroll
    for (int k = 0; k < 16; k++) sB += emis[i * NX + tid + 256 * k];
#pragma unroll
    for (int o = 16; o > 0; o >>= 1) {
        sA += __shfl_xor_sync(0xffffffffu, sA, o);
        sB += __shfl_xor_sync(0xffffffffu, sB, o);
    }
    if (lane == 0) { smA[w] = sA; smB[w] = sB; }
    __syncthreads();
    if (tid == 0) {
        float a = 0.f, b = 0.f;
#pragma unroll
        for (int j = 0; j < 8; j++) { a += smA[j]; b += smB[j]; }
        g_rinvA[i] = 1.0f / a;
        g_rinvB[i] = 1.0f / b;
    }
}

// ---------------------------------------------------------------------------
// K2: gather normalized emission columns: Bv[t][i] = emis[i][obs[t]] * rinvB[i]
// ---------------------------------------------------------------------------
__global__ void k_bv(const int* __restrict__ obs,
                     const float* __restrict__ emis) {
    int t = blockIdx.x;
    int o = __ldg(&obs[t]);
#pragma unroll
    for (int k = 0; k < 4; k++) {
        int i = threadIdx.x + 256 * k;
        g_Bv[t * NZ + i] = emis[i * NX + o] * g_rinvB[i];
    }
}

// ---------------------------------------------------------------------------
// K3: init — alpha[:,0] = log(pi * Bv0); publish p0; reset barrier counter.
// ---------------------------------------------------------------------------
__global__ void k_init(const float* __restrict__ sp,
                       float* __restrict__ alpha) {
    int tid = threadIdx.x, lane = tid & 31, w = tid >> 5;
    __shared__ float sm[32];
    __shared__ float bc_invS;

    float v = sp[tid];
    float s = v;
#pragma unroll
    for (int o = 16; o > 0; o >>= 1) s += __shfl_xor_sync(0xffffffffu, s, o);
    if (lane == 0) sm[w] = s;
    __syncthreads();
    if (tid == 0) {
        float a = 0.f;
#pragma unroll
        for (int j = 0; j < 32; j++) a += sm[j];
        bc_invS = 1.0f / a;
    }
    __syncthreads();

    float val = v * bc_invS * g_Bv[tid];   // t = 0 slice of Bv
    alpha[tid * NX] = logf(val);

    // Publish unnormalized p0; consumers normalize by the max they observe.
    __stcg(&g_pbuf[0][tid], val);
    if (tid == 0) {
        g_L0 = 0.0f;
        g_count = 0u;                      // reset barrier for graph replay
    }
}

// ---------------------------------------------------------------------------
// K4: persistent main loop. Warp w of CTA b owns row r = b*16 + w.
// Lane l holds A[r][4l + 128k + c], k=0..7, c=0..3 in registers.
// Published p is UNnormalized; each consumer computes max locally and divides.
// ---------------------------------------------------------------------------
__global__ void __launch_bounds__(MTHREADS, 1)
k_main(const float* __restrict__ trans, float* __restrict__ alpha) {
    __shared__ float ps[NZ];
    __shared__ float wmax[RPC];
    int tid = threadIdx.x, lane = tid & 31, w = tid >> 5;
    int r = blockIdx.x * RPC + w;

    // Load + normalize this row's A slice into registers (constant all steps)
    float rinv = g_rinvA[r];
    float4 A[8];
#pragma unroll
    for (int k = 0; k < 8; k++) {
        float4 a = *(const float4*)&trans[r * NZ + 4 * lane + 128 * k];
        a.x *= rinv; a.y *= rinv; a.z *= rinv; a.w *= rinv;
        A[k] = a;
    }

    float L = g_L0;
    float aacc = 0.f;            // per-lane alpha chunk buffer (lane t&31 owns t)

    for (int t = 1; t < NX; t++) {
        const float2* src = (const float2*)g_pbuf[(t - 1) & 1];
        float*        dst = g_pbuf[t & 1];

        // Barrier-independent prefetch for this step (hide L2 latency early)
        float bv = (lane == 0) ? __ldg(&g_Bv[t * NZ + r]) : 0.f;

        // Broadcast-load p~ (4 KB) into smem via L2 (.cg: L1 not coherent!)
        float2 p2 = __ldcg(&src[tid]);
        ((float2*)ps)[tid] = p2;
        float m = fmaxf(p2.x, p2.y);
#pragma unroll
        for (int o = 16; o > 0; o >>= 1) m = fmaxf(m, __shfl_xor_sync(0xffffffffu, m, o));
        if (lane == 0) wmax[w] = m;
        __syncthreads();

        // Row dot product: A (regs) x p~ (smem), 4 accumulators
        float a0 = 0.f, a1 = 0.f, a2 = 0.f, a3 = 0.f;
#pragma unroll
        for (int k = 0; k < 8; k++) {
            float4 p = *(const float4*)&ps[4 * lane + 128 * k];
            a0 = fmaf(A[k].x, p.x, a0);
            a1 = fmaf(A[k].y, p.y, a1);
            a2 = fmaf(A[k].z, p.z, a2);
            a3 = fmaf(A[k].w, p.w, a3);
        }
        float acc = (a0 + a1) + (a2 + a3);
#pragma unroll
        for (int o = 16; o > 0; o >>= 1) acc += __shfl_xor_sync(0xffffffffu, acc, o);

        float aval = 0.f;
        if (lane == 0) {
            float pmax = wmax[0];
#pragma unroll
            for (int j = 1; j < RPC; j++) pmax = fmaxf(pmax, wmax[j]);
            L += logf(pmax);                      // absorb scale into L
            float pn = (acc / pmax) * bv;         // next unnormalized p (bounded)
            __stcg(&dst[r], pn);                  // L2-coherent publish
            aval = L + logf(pn);
        }
        // Deposit alpha into the owning lane's register; flush every 32 steps.
        aval = __shfl_sync(0xffffffffu, aval, 0);
        if (lane == (t & 31)) aacc = aval;
        if ((t & 31) == 31) {
            int tbase = t & ~31;
            if (tbase + lane >= 1)                // chunk 0: lane 0 is t=0 (k_init's)
                alpha[r * NX + tbase + lane] = aacc;
        }

        // Grid barrier: release (fence + RED.ADD), acquire (poll + fence)
        __threadfence();
        __syncthreads();
        if (tid == 0) {
            atomicAdd(&g_count, 1u);
            unsigned int target = (unsigned int)t * (unsigned int)KCTA;
            while (*((volatile unsigned int*)&g_count) < target) { }
            __threadfence();
        }
        __syncthreads();
    }
}

// ---------------------------------------------------------------------------
extern "C" void kernel_launch(void* const* d_in, const int* in_sizes, int n_in,
                              void* d_out, int out_size) {
    const int*   obs   = (const int*)d_in[0];
    const float* sp    = (const float*)d_in[1];
    const float* trans = (const float*)d_in[2];
    const float* emis  = (const float*)d_in[3];
    float*       alpha = (float*)d_out;

    k_rowsums<<<NZ, 256>>>(trans, emis);
    k_bv<<<NX, 256>>>(obs, emis);
    k_init<<<1, 1024>>>(sp, alpha);
    k_main<<<KCTA, MTHREADS>>>(trans, alpha);
}

// round 4
// speedup vs baseline: 1.1782x; 1.1782x over previous
#include <cuda_runtime.h>

// HMM forward (log-space) as a scaled linear recurrence:
//   published p~_t (unnormalized, bounded: divided by max each step)
//   acc~[r] = sum_j A[r][j] * p~_{t-1}[j]   (pure fp32 matvec, A in registers)
//   alpha_t[r] = L_{t-1} + log(acc~[r]) + logBv[t][r]     (pmax-independent!)
//   p~_t[r]   = acc~[r] / pmax * Bv[t][r];  L_t = L_{t-1} + log(pmax)
//
// Persistent kernel, 64 CTAs x 512 thr (one wave), one warp per state row,
// A row in registers (32 floats/lane). Grid barrier: monotonic counter with
// red.release.gpu arrival + relaxed poll + fence.acq_rel.gpu (NO threadfence).
// Cross-CTA payload uses .cg (L2-coherent; L1 is NOT coherent across SMs).

#define NZ 1024
#define NX 4096
#define KCTA 64
#define RPC 16
#define MTHREADS 512

__device__ float        g_Bv[NX * NZ];     // Bv[t][i]    = B[i, obs[t]]   (16 MB)
__device__ float        g_logBv[NX * NZ];  // log(Bv[t][i])                (16 MB)
__device__ float        g_rinvA[NZ];
__device__ float        g_rinvB[NZ];
__device__ float        g_pbuf[2][NZ];
__device__ unsigned int g_count;

// ---------------------------------------------------------------------------
__global__ void k_rowsums(const float* __restrict__ trans,
                          const float* __restrict__ emis) {
    int i = blockIdx.x, tid = threadIdx.x, lane = tid & 31, w = tid >> 5;
    __shared__ float smA[8], smB[8];
    float sA = 0.f, sB = 0.f;
#pragma unroll
    for (int k = 0; k < 4; k++)  sA += trans[i * NZ + tid + 256 * k];
#pragma unroll
    for (int k = 0; k < 16; k++) sB += emis[i * NX + tid + 256 * k];
#pragma unroll
    for (int o = 16; o > 0; o >>= 1) {
        sA += __shfl_xor_sync(0xffffffffu, sA, o);
        sB += __shfl_xor_sync(0xffffffffu, sB, o);
    }
    if (lane == 0) { smA[w] = sA; smB[w] = sB; }
    __syncthreads();
    if (tid == 0) {
        float a = 0.f, b = 0.f;
#pragma unroll
        for (int j = 0; j < 8; j++) { a += smA[j]; b += smB[j]; }
        g_rinvA[i] = 1.0f / a;
        g_rinvB[i] = 1.0f / b;
    }
}

// ---------------------------------------------------------------------------
__global__ void k_bv(const int* __restrict__ obs,
                     const float* __restrict__ emis) {
    int t = blockIdx.x;
    int o = __ldg(&obs[t]);
#pragma unroll
    for (int k = 0; k < 4; k++) {
        int i = threadIdx.x + 256 * k;
        float v = emis[i * NX + o] * g_rinvB[i];
        g_Bv[t * NZ + i]    = v;
        g_logBv[t * NZ + i] = logf(v);    // precise log, precompute only
    }
}

// ---------------------------------------------------------------------------
__global__ void k_init(const float* __restrict__ sp,
                       float* __restrict__ alpha) {
    int tid = threadIdx.x, lane = tid & 31, w = tid >> 5;
    __shared__ float sm[32];
    __shared__ float bc_invS;

    float v = sp[tid];
    float s = v;
#pragma unroll
    for (int o = 16; o > 0; o >>= 1) s += __shfl_xor_sync(0xffffffffu, s, o);
    if (lane == 0) sm[w] = s;
    __syncthreads();
    if (tid == 0) {
        float a = 0.f;
#pragma unroll
        for (int j = 0; j < 32; j++) a += sm[j];
        bc_invS = 1.0f / a;
    }
    __syncthreads();

    float val = v * bc_invS * g_Bv[tid];   // t = 0 slice
    alpha[tid * NX] = logf(val);           // alpha_0 = L0(=0) + log p~0

    __stcg(&g_pbuf[0][tid], val);          // publish unnormalized p~0
    if (tid == 0) g_count = 0u;            // reset barrier for graph replay
}

// ---------------------------------------------------------------------------
// Persistent main loop. Warp w of CTA b owns row r = b*16 + w.
// Lane l holds A[r][4l + 128k + c], k=0..7, c=0..3 in registers.
// ---------------------------------------------------------------------------
__global__ void __launch_bounds__(MTHREADS, 1)
k_main(const float* __restrict__ trans, float* __restrict__ alpha) {
    __shared__ float ps[NZ];
    int tid = threadIdx.x, lane = tid & 31, w = tid >> 5;
    int r = blockIdx.x * RPC + w;

    float rinv = g_rinvA[r];
    float4 A[8];
#pragma unroll
    for (int k = 0; k < 8; k++) {
        float4 a = *(const float4*)&trans[r * NZ + 4 * lane + 128 * k];
        a.x *= rinv; a.y *= rinv; a.z *= rinv; a.w *= rinv;
        A[k] = a;
    }

    float L = 0.f;
    float aacc = 0.f;                       // alpha chunk buffer (lane t&31 owns t)
    // Prefetch step-1 emission factors (barrier-independent)
    float bv  = (lane == 0) ? __ldg(&g_Bv[NZ + r])    : 0.f;
    float lbv = (lane == 0) ? __ldg(&g_logBv[NZ + r]) : 0.f;

    for (int t = 1; t < NX; t++) {
        const float2* src = (const float2*)g_pbuf[(t - 1) & 1];
        float*        dst = g_pbuf[t & 1];

        // ---- acquire: wait until all CTAs published p~_{t-1} ----
        if (t > 1) {
            if (tid == 0) {
                unsigned int target = (unsigned int)(t - 1) * KCTA, v;
                do {
                    asm volatile("ld.relaxed.gpu.global.u32 %0, [%1];"
                                 : "=r"(v) : "l"(&g_count) : "memory");
                } while (v < target);
                asm volatile("fence.acq_rel.gpu;" ::: "memory");
            }
            __syncthreads();
        }

        // ---- cooperative p~ load: 4 KB from L2 into smem ----
        ((float2*)ps)[tid] = __ldcg(&src[tid]);
        __syncthreads();

        // ---- dot (A regs x p smem) with max folded into the same pass ----
        float a0 = 0.f, a1 = 0.f, a2 = 0.f, a3 = 0.f;
        float m0 = 0.f, m1 = 0.f, m2 = 0.f, m3 = 0.f;   // p~ > 0 always
#pragma unroll
        for (int k = 0; k < 8; k++) {
            float4 p = *(const float4*)&ps[4 * lane + 128 * k];
            a0 = fmaf(A[k].x, p.x, a0);  m0 = fmaxf(m0, p.x);
            a1 = fmaf(A[k].y, p.y, a1);  m1 = fmaxf(m1, p.y);
            a2 = fmaf(A[k].z, p.z, a2);  m2 = fmaxf(m2, p.z);
            a3 = fmaf(A[k].w, p.w, a3);  m3 = fmaxf(m3, p.w);
        }
        float acc = (a0 + a1) + (a2 + a3);
        float m   = fmaxf(fmaxf(m0, m1), fmaxf(m2, m3));
#pragma unroll
        for (int o = 16; o > 0; o >>= 1) {
            acc += __shfl_xor_sync(0xffffffffu, acc, o);
            m    = fmaxf(m, __shfl_xor_sync(0xffffffffu, m, o));
        }
        // All warps now hold identical pmax (exact: max is order-independent).

        // ---- publish ASAP (whole grid waits on this store) ----
        if (lane == 0)
            __stcg(&dst[r], __fdividef(acc, m) * bv);
        __syncthreads();
        if (tid == 0)
            asm volatile("red.release.gpu.global.add.u32 [%0], %1;"
                         :: "l"(&g_count), "r"(1u) : "memory");

        // ---- off-critical-path: alpha + L update + next prefetch ----
        float aval = 0.f;
        if (lane == 0) aval = L + __logf(acc) + lbv;    // pmax-independent
        L += __logf(m);
        aval = __shfl_sync(0xffffffffu, aval, 0);
        if (lane == (t & 31)) aacc = aval;
        if ((t & 31) == 31) {
            int tbase = t & ~31;
            if (tbase + lane >= 1)                       // lane0 of chunk0 = t0 (k_init)
                alpha[r * NX + tbase + lane] = aacc;
        }
        if (lane == 0 && t + 1 < NX) {                   // prefetch t+1 factors
            bv  = __ldg(&g_Bv[(t + 1) * NZ + r]);
            lbv = __ldg(&g_logBv[(t + 1) * NZ + r]);
        }
    }
}

// ---------------------------------------------------------------------------
extern "C" void kernel_launch(void* const* d_in, const int* in_sizes, int n_in,
                              void* d_out, int out_size) {
    const int*   obs   = (const int*)d_in[0];
    const float* sp    = (const float*)d_in[1];
    const float* trans = (const float*)d_in[2];
    const float* emis  = (const float*)d_in[3];
    float*       alpha = (float*)d_out;

    k_rowsums<<<NZ, 256>>>(trans, emis);
    k_bv<<<NX, 256>>>(obs, emis);
    k_init<<<1, 1024>>>(sp, alpha);
    k_main<<<KCTA, MTHREADS>>>(trans, alpha);
}

// round 6
// speedup vs baseline: 1.5849x; 1.3451x over previous
#include <cuda_runtime.h>

// HMM forward (log-space) as a scaled linear recurrence.
//   acc~[r] = sum_j A[r][j] * p~_{t-1}[j]       (A rows in registers)
//   alpha_t[r] = L_{t-1} + log(acc~[r]) + logBv[t][r]
//   p~_t[r] = acc~[r]/pmax * Bv[t][r];  L_t = L_{t-1} + log(pmax)
//
// Synchronization: NO barrier, NO counter. Each step t has its own slot
// g_pall[t][1024], poisoned to -1.0f before k_main. p~ > 0 always, so a
// positive value == "published". Consumers ld.volatile-spin directly on the
// data (32-bit loads are atomic; the datum is the flag -> zero fences, one
// L2 round trip per step instead of two).
//
// 64 CTAs x 512 thr (one wave), warp-per-row, shfl butterfly reductions.

#define NZ 1024
#define NX 4096
#define KCTA 64
#define RPC 16
#define MTHREADS 512

__device__ float g_Bv[NX * NZ];     // Bv[t][i] = B[i,obs[t]]       (16 MB)
__device__ float g_logBv[NX * NZ];  // log Bv                        (16 MB)
__device__ float g_pall[NX * NZ];   // per-step published p~ slots   (16 MB)
__device__ float g_rinvA[NZ];
__device__ float g_rinvB[NZ];

// ---------------------------------------------------------------------------
__global__ void k_rowsums(const float* __restrict__ trans,
                          const float* __restrict__ emis) {
    int i = blockIdx.x, tid = threadIdx.x, lane = tid & 31, w = tid >> 5;
    __shared__ float smA[8], smB[8];
    float sA = 0.f, sB = 0.f;
#pragma unroll
    for (int k = 0; k < 4; k++)  sA += trans[i * NZ + tid + 256 * k];
#pragma unroll
    for (int k = 0; k < 16; k++) sB += emis[i * NX + tid + 256 * k];
#pragma unroll
    for (int o = 16; o > 0; o >>= 1) {
        sA += __shfl_xor_sync(0xffffffffu, sA, o);
        sB += __shfl_xor_sync(0xffffffffu, sB, o);
    }
    if (lane == 0) { smA[w] = sA; smB[w] = sB; }
    __syncthreads();
    if (tid == 0) {
        float a = 0.f, b = 0.f;
#pragma unroll
        for (int j = 0; j < 8; j++) { a += smA[j]; b += smB[j]; }
        g_rinvA[i] = 1.0f / a;
        g_rinvB[i] = 1.0f / b;
    }
}

// ---------------------------------------------------------------------------
__global__ void k_bv(const int* __restrict__ obs,
                     const float* __restrict__ emis) {
    int t = blockIdx.x;
    int o = __ldg(&obs[t]);
#pragma unroll
    for (int k = 0; k < 4; k++) {
        int i = threadIdx.x + 256 * k;
        float v = emis[i * NX + o] * g_rinvB[i];
        g_Bv[t * NZ + i]    = v;
        g_logBv[t * NZ + i] = logf(v);
    }
}

// ---------------------------------------------------------------------------
// Poison all publish slots to -1 (graph replays re-run this; stream-ordered
// before k_init/k_main so no race).
// ---------------------------------------------------------------------------
__global__ void k_poison() {
    int idx = (blockIdx.x * 256 + threadIdx.x) * 4;
    float4 v = make_float4(-1.f, -1.f, -1.f, -1.f);
    *(float4*)&g_pall[idx] = v;
}

// ---------------------------------------------------------------------------
__global__ void k_init(const float* __restrict__ sp,
                       float* __restrict__ alpha) {
    int tid = threadIdx.x, lane = tid & 31, w = tid >> 5;
    __shared__ float sm[32];
    __shared__ float bc_invS;

    float v = sp[tid];
    float s = v;
#pragma unroll
    for (int o = 16; o > 0; o >>= 1) s += __shfl_xor_sync(0xffffffffu, s, o);
    if (lane == 0) sm[w] = s;
    __syncthreads();
    if (tid == 0) {
        float a = 0.f;
#pragma unroll
        for (int j = 0; j < 32; j++) a += sm[j];
        bc_invS = 1.0f / a;
    }
    __syncthreads();

    float val = v * bc_invS * g_Bv[tid];   // t = 0 slice
    alpha[tid * NX] = logf(val);           // alpha_0 = log p~0  (L0 = 0)
    __stcg(&g_pall[tid], val);             // publish slot t = 0
}

// ---------------------------------------------------------------------------
// Persistent main loop. Warp w of CTA b owns row r = b*16 + w.
// Lane l holds A[r][4l + 128k + c] in registers.
// ---------------------------------------------------------------------------
__global__ void __launch_bounds__(MTHREADS, 1)
k_main(const float* __restrict__ trans, float* __restrict__ alpha) {
    __shared__ float ps[NZ];
    int tid = threadIdx.x, lane = tid & 31, w = tid >> 5;
    int r = blockIdx.x * RPC + w;

    float rinv = g_rinvA[r];
    float4 A[8];
#pragma unroll
    for (int k = 0; k < 8; k++) {
        float4 a = *(const float4*)&trans[r * NZ + 4 * lane + 128 * k];
        a.x *= rinv; a.y *= rinv; a.z *= rinv; a.w *= rinv;
        A[k] = a;
    }

    float L = 0.f;
    float aacc = 0.f;                        // alpha chunk buffer
    float bv  = (lane == 0) ? __ldg(&g_Bv[NZ + r])    : 0.f;
    float lbv = (lane == 0) ? __ldg(&g_logBv[NZ + r]) : 0.f;

    for (int t = 1; t < NX; t++) {
        const float* src = &g_pall[(t - 1) * NZ];
        float*       dst = &g_pall[t * NZ];

        // ---- spin directly on this thread's slice of step-(t-1) data ----
        float x0, x1;
        const float* a0p = src + 2 * tid;
        do {
            asm volatile("ld.volatile.global.v2.f32 {%0,%1}, [%2];"
                         : "=f"(x0), "=f"(x1) : "l"(a0p) : "memory");
        } while (x0 < 0.f || x1 < 0.f);
        ps[2 * tid]     = x0;
        ps[2 * tid + 1] = x1;
        __syncthreads();

        // ---- dot (A regs x p smem), max folded into the same pass ----
        float s0 = 0.f, s1 = 0.f, s2 = 0.f, s3 = 0.f;
        float m0 = 0.f, m1 = 0.f, m2 = 0.f, m3 = 0.f;
#pragma unroll
        for (int k = 0; k < 8; k++) {
            float4 p = *(const float4*)&ps[4 * lane + 128 * k];
            s0 = fmaf(A[k].x, p.x, s0);  m0 = fmaxf(m0, p.x);
            s1 = fmaf(A[k].y, p.y, s1);  m1 = fmaxf(m1, p.y);
            s2 = fmaf(A[k].z, p.z, s2);  m2 = fmaxf(m2, p.z);
            s3 = fmaf(A[k].w, p.w, s3);  m3 = fmaxf(m3, p.w);
        }
        float acc = (s0 + s1) + (s2 + s3);
        float m   = fmaxf(fmaxf(m0, m1), fmaxf(m2, m3));
#pragma unroll
        for (int o = 16; o > 0; o >>= 1) {   // interleaved: add/max dual-issue
            acc += __shfl_xor_sync(0xffffffffu, acc, o);
            m    = fmaxf(m, __shfl_xor_sync(0xffffffffu, m, o));
        }
        // All warps hold identical pmax (max order-independent); acc is the
        // row dot, identical across the warp after the butterfly.

        // ---- publish ASAP (the whole grid spins on this store) ----
        if (lane == 0)
            __stcg(&dst[r], __fdividef(acc, m) * bv);

        // ---- off critical path: alpha, L, prefetch ----
        float aval = 0.f;
        if (lane == 0) aval = L + __logf(acc) + lbv;   // pmax-independent
        L += __logf(m);
        aval = __shfl_sync(0xffffffffu, aval, 0);
        if (lane == (t & 31)) aacc = aval;
        if ((t & 31) == 31) {
            int tbase = t & ~31;
            if (tbase + lane >= 1)                      // t=0 written by k_init
                alpha[r * NX + tbase + lane] = aacc;
        }
        if (lane == 0 && t + 1 < NX) {
            bv  = __ldg(&g_Bv[(t + 1) * NZ + r]);
            lbv = __ldg(&g_logBv[(t + 1) * NZ + r]);
        }
        __syncthreads();   // protect ps before next step overwrites it
    }
}

// ---------------------------------------------------------------------------
extern "C" void kernel_launch(void* const* d_in, const int* in_sizes, int n_in,
                              void* d_out, int out_size) {
    const int*   obs   = (const int*)d_in[0];
    const float* sp    = (const float*)d_in[1];
    const float* trans = (const float*)d_in[2];
    const float* emis  = (const float*)d_in[3];
    float*       alpha = (float*)d_out;

    k_rowsums<<<NZ, 256>>>(trans, emis);
    k_bv<<<NX, 256>>>(obs, emis);
    k_poison<<<(NX * NZ) / (256 * 4), 256>>>();
    k_init<<<1, 1024>>>(sp, alpha);
    k_main<<<KCTA, MTHREADS>>>(trans, alpha);
}